// round 13
// baseline (speedup 1.0000x reference)
#include <cuda_runtime.h>
#include <cuda_bf16.h>
#include <cstdint>

#define BLOCK 448
#define NROWS 262144
#define NBLKS ((NROWS + BLOCK - 1) / BLOCK)   // 586
#define GRID 148                               // persistent: 1 CTA/SM

constexpr int KPAD = 72;   // weight k stride (bf16) -> conflict-free B loads
constexpr int APAD = 56;   // acts col stride (bf16) -> conflict-free A loads
constexpr int DPAD = 73;   // D scratch stride (f32) -> conflict-free reads

// ---------------- scal float offsets ----------------
constexpr int F_UH1W=0, F_UH1B=104, F_G1W=112, F_G1B=176, F_G2W=184, F_G2B=192,
    F_UZ1=196, F_UZ2S=228, F_UZ2Z=292, F_DG1W=300, F_DG1B=364, F_DG2W=372,
    F_DG2B=380, F_DZ2S=384, F_DZ2Z=448, F_B1=456, F_B2=520, F_B3=584,
    F_FB1=656, F_FB2=720, F_FB3=784;   // 792 floats

// ---------------- smem layout ----------------
constexpr int SM_WT = 3584;
constexpr int WH_L1=0,     WL_L1=4608,  WH_L2=9216,  WL_L2=13824,
              WH_L3=18432, WL_L3=23616, WH_F1=28800, WL_F1=33408,
              WH_F2=38016, WL_F2=42624, WH_F3=47232, WL_F3=47808;  // end 48384 elems
constexpr int SM_WARP  = SM_WT + 48384 * 2;      // 100352
constexpr int WARP_BLK = 32 * DPAD * 4;          // 9344 (acts 7168 overlays D region)
constexpr int NWARPS   = BLOCK / 32;             // 14
constexpr int SMEM_BYTES = SM_WARP + NWARPS * WARP_BLK;   // 231168

// gram pair index -> (a,b)
__device__ const unsigned char PA[36] = {0,0,0,0,0,0,0,0, 1,1,1,1,1,1,1, 2,2,2,2,2,2,
                                         3,3,3,3,3, 4,4,4,4, 5,5,5, 6,6, 7};
__device__ const unsigned char PB[36] = {0,1,2,3,4,5,6,7, 1,2,3,4,5,6,7, 2,3,4,5,6,7,
                                         3,4,5,6,7, 4,5,6,7, 5,6,7, 6,7, 7};

// ---------------- helpers ----------------
__device__ __forceinline__ void cvt2(float v0, float v1, uint32_t& hp, uint32_t& lp) {
    __nv_bfloat16 h0 = __float2bfloat16(v0), h1 = __float2bfloat16(v1);
    float r0 = v0 - __bfloat162float(h0), r1 = v1 - __bfloat162float(h1);
    __nv_bfloat16 l0 = __float2bfloat16(r0), l1 = __float2bfloat16(r1);
    __nv_bfloat162 hh; hh.x = h0; hh.y = h1;
    __nv_bfloat162 ll; ll.x = l0; ll.y = l1;
    hp = *reinterpret_cast<uint32_t*>(&hh);
    lp = *reinterpret_cast<uint32_t*>(&ll);
}

__device__ __forceinline__ void mma16816(float* d, const uint32_t* a, uint32_t b0, uint32_t b1) {
    asm volatile(
        "mma.sync.aligned.m16n8k16.row.col.f32.bf16.bf16.f32 "
        "{%0,%1,%2,%3}, {%4,%5,%6,%7}, {%8,%9}, {%0,%1,%2,%3};"
        : "+f"(d[0]), "+f"(d[1]), "+f"(d[2]), "+f"(d[3])
        : "r"(a[0]), "r"(a[1]), "r"(a[2]), "r"(a[3]), "r"(b0), "r"(b1));
}

// Layer with A from registers; NTOFF = output-tile offset (weights+bias rows).
template<int KT, int NT>
__device__ __forceinline__ void layer_rr(const float (&p)[2][2*KT][4], float (&dn)[2][NT][4],
                                         const uint16_t* WH, const uint16_t* WL,
                                         const float* bias, int gid, int tig, int ntOff = 0) {
#pragma unroll
    for (int mt = 0; mt < 2; mt++)
#pragma unroll
        for (int nt = 0; nt < NT; nt++) {
            float2 b = *reinterpret_cast<const float2*>(bias + (ntOff + nt) * 8 + 2 * tig);
            dn[mt][nt][0] = b.x; dn[mt][nt][1] = b.y;
            dn[mt][nt][2] = b.x; dn[mt][nt][3] = b.y;
        }
#pragma unroll
    for (int kt = 0; kt < KT; kt++) {
        uint32_t aH[2][4], aL[2][4];
#pragma unroll
        for (int mt = 0; mt < 2; mt++) {
            cvt2(p[mt][2*kt][0],   p[mt][2*kt][1],   aH[mt][0], aL[mt][0]);
            cvt2(p[mt][2*kt][2],   p[mt][2*kt][3],   aH[mt][1], aL[mt][1]);
            cvt2(p[mt][2*kt+1][0], p[mt][2*kt+1][1], aH[mt][2], aL[mt][2]);
            cvt2(p[mt][2*kt+1][2], p[mt][2*kt+1][3], aH[mt][3], aL[mt][3]);
        }
#pragma unroll
        for (int nt = 0; nt < NT; nt++) {
            const uint32_t* ph = reinterpret_cast<const uint32_t*>(WH + ((ntOff+nt)*8+gid)*KPAD + kt*16 + 2*tig);
            const uint32_t* pl = reinterpret_cast<const uint32_t*>(WL + ((ntOff+nt)*8+gid)*KPAD + kt*16 + 2*tig);
            uint32_t bh0 = ph[0], bh1 = ph[4], bl0 = pl[0], bl1 = pl[4];
#pragma unroll
            for (int mt = 0; mt < 2; mt++) {
                mma16816(dn[mt][nt], aH[mt], bh0, bh1);
                mma16816(dn[mt][nt], aH[mt], bl0, bl1);
                mma16816(dn[mt][nt], aL[mt], bh0, bh1);
            }
        }
    }
}

// Layer with A from smem acts (hi/lo planes, APAD stride).
template<int KT, int NT>
__device__ __forceinline__ void layer_sm(const uint16_t* actH, const uint16_t* actL,
                                         float (&dn)[2][NT][4],
                                         const uint16_t* WH, const uint16_t* WL,
                                         const float* bias, int gid, int tig) {
#pragma unroll
    for (int mt = 0; mt < 2; mt++)
#pragma unroll
        for (int nt = 0; nt < NT; nt++) {
            float2 b = *reinterpret_cast<const float2*>(bias + nt * 8 + 2 * tig);
            dn[mt][nt][0] = b.x; dn[mt][nt][1] = b.y;
            dn[mt][nt][2] = b.x; dn[mt][nt][3] = b.y;
        }
#pragma unroll
    for (int kt = 0; kt < KT; kt++) {
        uint32_t aH[2][4], aL[2][4];
#pragma unroll
        for (int mt = 0; mt < 2; mt++) {
            const int r0 = mt * 16 + gid, c0 = kt * 16 + 2 * tig;
            aH[mt][0] = *reinterpret_cast<const uint32_t*>(actH + r0 * APAD + c0);
            aH[mt][1] = *reinterpret_cast<const uint32_t*>(actH + (r0 + 8) * APAD + c0);
            aH[mt][2] = *reinterpret_cast<const uint32_t*>(actH + r0 * APAD + c0 + 8);
            aH[mt][3] = *reinterpret_cast<const uint32_t*>(actH + (r0 + 8) * APAD + c0 + 8);
            aL[mt][0] = *reinterpret_cast<const uint32_t*>(actL + r0 * APAD + c0);
            aL[mt][1] = *reinterpret_cast<const uint32_t*>(actL + (r0 + 8) * APAD + c0);
            aL[mt][2] = *reinterpret_cast<const uint32_t*>(actL + r0 * APAD + c0 + 8);
            aL[mt][3] = *reinterpret_cast<const uint32_t*>(actL + (r0 + 8) * APAD + c0 + 8);
        }
#pragma unroll
        for (int nt = 0; nt < NT; nt++) {
            const uint32_t* ph = reinterpret_cast<const uint32_t*>(WH + (nt*8+gid)*KPAD + kt*16 + 2*tig);
            const uint32_t* pl = reinterpret_cast<const uint32_t*>(WL + (nt*8+gid)*KPAD + kt*16 + 2*tig);
            uint32_t bh0 = ph[0], bh1 = ph[4], bl0 = pl[0], bl1 = pl[4];
#pragma unroll
            for (int mt = 0; mt < 2; mt++) {
                mma16816(dn[mt][nt], aH[mt], bh0, bh1);
                mma16816(dn[mt][nt], aH[mt], bl0, bl1);
                mma16816(dn[mt][nt], aL[mt], bh0, bh1);
            }
        }
    }
}

template<int NT>
__device__ __forceinline__ void relu_d(float (&d)[2][NT][4]) {
#pragma unroll
    for (int mt = 0; mt < 2; mt++)
#pragma unroll
        for (int nt = 0; nt < NT; nt++)
#pragma unroll
            for (int i = 0; i < 4; i++) d[mt][nt][i] = fmaxf(d[mt][nt][i], 0.f);
}

template<int NT>
__device__ __forceinline__ void store_D(float* dscr, const float (&d)[2][NT][4],
                                        int gid, int tig, int ntOff = 0) {
#pragma unroll
    for (int mt = 0; mt < 2; mt++)
#pragma unroll
        for (int nt = 0; nt < NT; nt++) {
            const int c = (ntOff + nt) * 8 + 2 * tig;
            dscr[(mt*16+gid)*DPAD + c]     = d[mt][nt][0];
            dscr[(mt*16+gid)*DPAD + c + 1] = d[mt][nt][1];
            dscr[(mt*16+gid+8)*DPAD + c]     = d[mt][nt][2];
            dscr[(mt*16+gid+8)*DPAD + c + 1] = d[mt][nt][3];
        }
}

__device__ __forceinline__ void write_acts(uint16_t* actH, uint16_t* actL, int lane, const float* xv) {
    uint32_t* ah = reinterpret_cast<uint32_t*>(actH + lane * APAD);
    uint32_t* al = reinterpret_cast<uint32_t*>(actL + lane * APAD);
#pragma unroll
    for (int c = 0; c < 48; c += 2) {
        float v0 = (c < 44) ? xv[c] : 0.f;
        float v1 = (c + 1 < 44) ? xv[c + 1] : 0.f;
        uint32_t hp, lp; cvt2(v0, v1, hp, lp);
        ah[c / 2] = hp; al[c / 2] = lp;
    }
}

__global__ void __launch_bounds__(BLOCK, 1) frame_gnn_mma_kernel(
    const float* __restrict__ state,
    const float* __restrict__ up_Z1_w, const float* __restrict__ up_h1_w, const float* __restrict__ up_h1_b,
    const float* __restrict__ up_g1_w1, const float* __restrict__ up_g1_b1,
    const float* __restrict__ up_g1_w2, const float* __restrict__ up_g1_b2,
    const float* __restrict__ up_Z2_w,
    const float* __restrict__ up_m_w1, const float* __restrict__ up_m_b1,
    const float* __restrict__ up_m_w2, const float* __restrict__ up_m_b2,
    const float* __restrict__ up_m_w3, const float* __restrict__ up_m_b3,
    const float* __restrict__ dn_g1_w1, const float* __restrict__ dn_g1_b1,
    const float* __restrict__ dn_g1_w2, const float* __restrict__ dn_g1_b2,
    const float* __restrict__ dn_Z2_w,
    const float* __restrict__ fr_w1, const float* __restrict__ fr_b1,
    const float* __restrict__ fr_w2, const float* __restrict__ fr_b2,
    const float* __restrict__ fr_w3, const float* __restrict__ fr_b3,
    float* __restrict__ out)
{
    extern __shared__ char smc[];
    float* scal = reinterpret_cast<float*>(smc);
    uint16_t* WT = reinterpret_cast<uint16_t*>(smc + SM_WT);
    const int tid = threadIdx.x;

    // ---------------- stage scalar weights (once) ----------------
    for (int i = tid; i < 104; i += BLOCK) scal[F_UH1W + i] = up_h1_w[i];
    for (int i = tid; i < 32; i += BLOCK)  scal[F_UZ1 + i] = up_Z1_w[i];
    for (int i = tid; i < 64; i += BLOCK) {
        const int k = i >> 3, j = i & 7;
        scal[F_G1W + i]  = up_g1_w1[k * 24 + j];
        scal[F_DG1W + i] = dn_g1_w1[k * 16 + j];
        scal[F_UZ2S + i] = up_Z2_w[k * 25 + j];
        scal[F_DZ2S + i] = dn_Z2_w[k * 17 + j];
        scal[F_B1 + i] = up_m_b1[i];  scal[F_B2 + i] = up_m_b2[i];
        scal[F_FB1 + i] = fr_b1[i];   scal[F_FB2 + i] = fr_b2[i];
    }
    for (int i = tid; i < 72; i += BLOCK) scal[F_B3 + i] = up_m_b3[i];
    if (tid < 8) {
        scal[F_UH1B + tid] = up_h1_b[tid];
        scal[F_G1B + tid]  = up_g1_b1[tid];
        scal[F_G2W + tid]  = up_g1_w2[tid];
        scal[F_UZ2Z + tid] = up_Z2_w[tid * 25 + 24];
        scal[F_DG1B + tid] = dn_g1_b1[tid];
        scal[F_DG2W + tid] = dn_g1_w2[tid];
        scal[F_DZ2Z + tid] = dn_Z2_w[tid * 17 + 16];
        scal[F_FB3 + tid]  = fr_b3[tid];
    }
    if (tid == 0) { scal[F_G2B] = up_g1_b2[0]; scal[F_DG2B] = dn_g1_b2[0]; }

    // ---------------- stage weight matrices (bf16 split, [n][KPAD], once) --------
    auto wsplit = [&](int offH, int offL, int idx, float v) {
        __nv_bfloat16 h = __float2bfloat16(v);
        __nv_bfloat16 l = __float2bfloat16(v - __bfloat162float(h));
        WT[offH + idx] = *reinterpret_cast<uint16_t*>(&h);
        WT[offL + idx] = *reinterpret_cast<uint16_t*>(&l);
    };
    for (int e = tid; e < 64 * KPAD; e += BLOCK) {   // L1 / F1 (folded gram)
        const int n = e / KPAD, k = e % KPAD;
        float v1 = 0.f, vf = 0.f;
        if (k < 36) {
            const int a = PA[k], b = PB[k];
            v1 = up_m_w1[n * 88 + a * 8 + b];
            vf = fr_w1[n * 80 + a * 8 + b];
            if (a != b) { v1 += up_m_w1[n * 88 + b * 8 + a]; vf += fr_w1[n * 80 + b * 8 + a]; }
        } else if (k < 44) {
            v1 = up_m_w1[n * 88 + 64 + (k - 36)];
            vf = fr_w1[n * 80 + 64 + (k - 36)];
        }
        wsplit(WH_L1, WL_L1, e, v1);
        wsplit(WH_F1, WL_F1, e, vf);
    }
    for (int e = tid; e < 64 * KPAD; e += BLOCK) {   // L2 / F2
        const int n = e / KPAD, k = e % KPAD;
        float v2 = (k < 64) ? up_m_w2[n * 64 + k] : 0.f;
        float vg = (k < 64) ? fr_w2[n * 64 + k] : 0.f;
        wsplit(WH_L2, WL_L2, e, v2);
        wsplit(WH_F2, WL_F2, e, vg);
    }
    for (int e = tid; e < 72 * KPAD; e += BLOCK) {   // L3
        const int n = e / KPAD, k = e % KPAD;
        wsplit(WH_L3, WL_L3, e, (k < 64) ? up_m_w3[n * 64 + k] : 0.f);
    }
    for (int e = tid; e < 8 * KPAD; e += BLOCK) {    // F3
        const int n = e / KPAD, k = e % KPAD;
        wsplit(WH_F3, WL_F3, e, (k < 64) ? fr_w3[n * 64 + k] : 0.f);
    }
    __syncthreads();

    const int w = tid >> 5, lane = tid & 31;
    const int gid = lane >> 2, tig = lane & 3;
    uint16_t* actH = reinterpret_cast<uint16_t*>(smc + SM_WARP + w * WARP_BLK);
    uint16_t* actL = actH + 32 * APAD;
    float* dscr = reinterpret_cast<float*>(smc + SM_WARP + w * WARP_BLK);

    // ---------------- persistent chunk loop ----------------
    for (int blk = blockIdx.x; blk < NBLKS; blk += GRID) {
        int row = blk * BLOCK + tid;
        if (row >= NROWS) row = NROWS - 1;   // dup rows write identical values
        const float* s = state + (size_t)row * 25;
        float* o = out + (size_t)row * 25;

        // ---------------- front (SIMT) ----------------
        float h0[13];
#pragma unroll
        for (int i = 0; i < 4; i++) { float v = s[i]; h0[i] = v; o[i] = v; }
#pragma unroll
        for (int i = 0; i < 9; i++) { float v = s[16 + i]; h0[4 + i] = v; o[16 + i] = v; }
        float hm8[8];
#pragma unroll
        for (int k = 0; k < 8; k++) {
            float a = scal[F_UH1B + k];
#pragma unroll
            for (int i = 0; i < 13; i++) a += h0[i] * scal[F_UH1W + k * 13 + i];
            hm8[k] = fmaxf(a, 0.f);
        }
        float gs = scal[F_G2B];
#pragma unroll
        for (int k = 0; k < 8; k++) {
            float a = scal[F_G1B + k];
#pragma unroll
            for (int i = 0; i < 8; i++) a += hm8[i] * scal[F_G1W + k * 8 + i];
            gs += fmaxf(a, 0.f) * scal[F_G2W + k];
        }
        float Zm0[8], Zm1[8], Zm2[8];
        {
            float Z0x[4], Z0y[4], Z0z[4];
#pragma unroll
            for (int j = 0; j < 4; j++) { Z0x[j] = s[4 + 3 * j]; Z0y[j] = s[5 + 3 * j]; Z0z[j] = s[6 + 3 * j]; }
            float Zu0[8], Zu1[8], Zu2[8];
#pragma unroll
            for (int k = 0; k < 8; k++) {
                float a0 = 0.f, a1 = 0.f, a2 = 0.f;
#pragma unroll
                for (int j = 0; j < 4; j++) {
                    float wv = scal[F_UZ1 + k * 4 + j];
                    a0 += Z0x[j] * wv; a1 += Z0y[j] * wv; a2 += Z0z[j] * wv;
                }
                Zu0[k] = a0; Zu1[k] = a1; Zu2[k] = a2;
            }
#pragma unroll
            for (int k = 0; k < 8; k++) {
                float a0 = 0.f, a1 = 0.f, a2 = 0.f;
#pragma unroll
                for (int m = 0; m < 8; m++) {
                    float wv = scal[F_UZ2S + k * 8 + m];
                    a0 += Zu0[m] * wv; a1 += Zu1[m] * wv; a2 += Zu2[m] * wv;
                }
                a2 += gs * scal[F_UZ2Z + k];
                Zm0[k] = a0; Zm1[k] = a1; Zm2[k] = a2;
            }
        }
        float xv[44], nrm = 0.f;
        {
            int p = 0;
#pragma unroll
            for (int a = 0; a < 8; a++)
#pragma unroll
                for (int b = a; b < 8; b++) {
                    float v = Zm0[a] * Zm0[b] + Zm1[a] * Zm1[b] + Zm2[a] * Zm2[b];
                    xv[p] = v;
                    nrm += (a == b) ? v * v : 2.f * v * v;
                    p++;
                }
        }
#pragma unroll
        for (int j = 0; j < 8; j++) xv[36 + j] = hm8[j];
        const float invFn = 1.f / (sqrtf(nrm) + 1.f);

        write_acts(actH, actL, lane, xv);
        __syncwarp();

        // ---------------- up_m chain: L1 -> L2 -> L3 (L3 in two passes) ----------
        float d1[2][8][4];
        layer_sm<3, 8>(actH, actL, d1, WT + WH_L1, WT + WL_L1, scal + F_B1, gid, tig);
        relu_d<8>(d1);
        float d2[2][8][4];
        layer_rr<4, 8>(d1, d2, WT + WH_L2, WT + WL_L2, scal + F_B2, gid, tig);
        relu_d<8>(d2);
        __syncwarp();              // acts reads done before D overwrites scratch
        {
            float d3a[2][5][4];
            layer_rr<4, 5>(d2, d3a, WT + WH_L3, WT + WL_L3, scal + F_B3, gid, tig, 0);
            store_D<5>(dscr, d3a, gid, tig, 0);
        }
        {
            float d3b[2][4][4];
            layer_rr<4, 4>(d2, d3b, WT + WH_L3, WT + WL_L3, scal + F_B3, gid, tig, 5);
            store_D<4>(dscr, d3b, gid, tig, 5);
        }
        __syncwarp();

        // ---------------- L3 post (row-coupled SIMT, streamed from smem) ---------
        float Yx[8], Yy[8], invFn2;
        {
            const float* dr = dscr + lane * DPAD;
            float uZ0[8], uZ1[8], uZ2[8], hm2[8];
#pragma unroll
            for (int k = 0; k < 8; k++) { uZ0[k] = 0.f; uZ1[k] = 0.f; uZ2[k] = 0.f; }
#pragma unroll
            for (int j = 0; j < 8; j++) {
                const float zj0 = Zm0[j], zj1 = Zm1[j], zj2 = Zm2[j];
#pragma unroll
                for (int k = 0; k < 8; k++) {
                    float m = dr[j * 8 + k] * invFn;   // bias baked into acc init
                    uZ0[k] += zj0 * m; uZ1[k] += zj1 * m; uZ2[k] += zj2 * m;
                }
            }
#pragma unroll
            for (int j = 0; j < 8; j++)
                hm2[j] = fmaxf(dr[64 + j] * invFn, 0.f);
            float gs2 = scal[F_DG2B];
#pragma unroll
            for (int k = 0; k < 8; k++) {
                float a = scal[F_DG1B + k];
#pragma unroll
                for (int i = 0; i < 8; i++) a += hm2[i] * scal[F_DG1W + k * 8 + i];
                gs2 += fmaxf(a, 0.f) * scal[F_DG2W + k];
            }
            float Yz[8];
#pragma unroll
            for (int k = 0; k < 8; k++) {
                float a0 = 0.f, a1 = 0.f, a2 = 0.f;
#pragma unroll
                for (int j = 0; j < 8; j++) {
                    float wv = scal[F_DZ2S + k * 8 + j];
                    a0 += uZ0[j] * wv; a1 += uZ1[j] * wv; a2 += uZ2[j] * wv;
                }
                a2 += gs2 * scal[F_DZ2Z + k];
                Yx[k] = a0; Yy[k] = a1; Yz[k] = a2;
            }
            float nrm2 = 0.f;
            int p = 0;
#pragma unroll
            for (int a = 0; a < 8; a++)
#pragma unroll
                for (int b = a; b < 8; b++) {
                    float v = Yx[a] * Yx[b] + Yy[a] * Yy[b] + Yz[a] * Yz[b];
                    xv[p] = v;
                    nrm2 += (a == b) ? v * v : 2.f * v * v;
                    p++;
                }
#pragma unroll
            for (int j = 0; j < 8; j++) xv[36 + j] = hm2[j];
            invFn2 = 1.f / (sqrtf(nrm2) + 1.f);
        }
        __syncwarp();              // D reads done before acts overwrite
        write_acts(actH, actL, lane, xv);
        __syncwarp();

        // ---------------- fr chain: F1 -> F2 -> F3 ----------------
        float f1[2][8][4];
        layer_sm<3, 8>(actH, actL, f1, WT + WH_F1, WT + WL_F1, scal + F_FB1, gid, tig);
        relu_d<8>(f1);
        float f2[2][8][4];
        layer_rr<4, 8>(f1, f2, WT + WH_F2, WT + WL_F2, scal + F_FB2, gid, tig);
        relu_d<8>(f2);
        float f3[2][1][4];
        layer_rr<4, 1>(f2, f3, WT + WH_F3, WT + WL_F3, scal + F_FB3, gid, tig);
        __syncwarp();              // acts reads done before D overwrites
        store_D<1>(dscr, f3, gid, tig);
        __syncwarp();

        // ---------------- frame + rotation + writeback (frv streamed) ------------
        float fx = 0.f, fy = 0.f;
        {
            const float* dr = dscr + lane * DPAD;
#pragma unroll
            for (int k = 0; k < 8; k++) {
                float fv = dr[k] * invFn2;
                fx += Yx[k] * fv; fy += Yy[k] * fv;
            }
        }
        const float nn = sqrtf(fx * fx + fy * fy) + 1e-6f;
        const float u1x = fx / nn, u1y = fy / nn;
#pragma unroll
        for (int j = 0; j < 4; j++) {
            const float zx = __ldg(&s[4 + 3 * j]);
            const float zy = __ldg(&s[5 + 3 * j]);
            const float zz = __ldg(&s[6 + 3 * j]);
            o[4 + 3 * j]     = u1x * zx + u1y * zy;
            o[4 + 3 * j + 1] = -u1y * zx + u1x * zy;
            o[4 + 3 * j + 2] = zz;
        }
        __syncwarp();              // dscr reads done before next chunk's acts
    }
}

extern "C" void kernel_launch(void* const* d_in, const int* in_sizes, int n_in,
                              void* d_out, int out_size) {
    (void)in_sizes; (void)n_in; (void)out_size;
    cudaFuncSetAttribute(frame_gnn_mma_kernel, cudaFuncAttributeMaxDynamicSharedMemorySize,
                         SMEM_BYTES);
    frame_gnn_mma_kernel<<<GRID, BLOCK, SMEM_BYTES>>>(
        (const float*)d_in[0],
        (const float*)d_in[1], (const float*)d_in[2], (const float*)d_in[3],
        (const float*)d_in[4], (const float*)d_in[5], (const float*)d_in[6], (const float*)d_in[7],
        (const float*)d_in[8],
        (const float*)d_in[9], (const float*)d_in[10], (const float*)d_in[11], (const float*)d_in[12],
        (const float*)d_in[13], (const float*)d_in[14],
        (const float*)d_in[15], (const float*)d_in[16], (const float*)d_in[17], (const float*)d_in[18],
        (const float*)d_in[19],
        (const float*)d_in[20], (const float*)d_in[21], (const float*)d_in[22], (const float*)d_in[23],
        (const float*)d_in[24], (const float*)d_in[25],
        (float*)d_out);
}

// round 15
// speedup vs baseline: 1.0433x; 1.0433x over previous
#include <cuda_runtime.h>
#include <cuda_bf16.h>
#include <cstdint>

#define BLOCK 448
#define NROWS 262144
#define NBLKS ((NROWS + BLOCK - 1) / BLOCK)   // 586
#define GRID 148                               // persistent: 1 CTA/SM

constexpr int KPAD = 72;   // weight k stride (bf16) -> conflict-free B loads
constexpr int APAD = 56;   // acts col stride (bf16) -> conflict-free A loads
constexpr int DPAD = 73;   // D scratch stride (f32) -> conflict-free reads
constexpr int FWRD = 68;   // fragbuf words per thread (64 + 4 pad) -> conflict-free uint4

// ---------------- scal float offsets ----------------
constexpr int F_UH1W=0, F_UH1B=104, F_G1W=112, F_G1B=176, F_G2W=184, F_G2B=192,
    F_UZ1=196, F_UZ2S=228, F_UZ2Z=292, F_DG1W=300, F_DG1B=364, F_DG2W=372,
    F_DG2B=380, F_DZ2S=384, F_DZ2Z=448, F_B1=456, F_B2=520, F_B3=584,
    F_FB1=656, F_FB2=720, F_FB3=784;   // 792 floats

// ---------------- smem layout ----------------
constexpr int SM_WT = 3584;
constexpr int WH_L1=0,     WL_L1=4608,  WH_L2=9216,  WL_L2=13824,
              WH_L3=18432, WL_L3=23616, WH_F1=28800, WL_F1=33408,
              WH_F2=38016, WL_F2=42624, WH_F3=47232, WL_F3=47808;  // end 48384 elems
constexpr int SM_WARP  = SM_WT + 48384 * 2;      // 100352
constexpr int WARP_BLK = 32 * DPAD * 4;          // 9344; holds acts(7168) | fragbuf(8704) | D(9344), time-shared
constexpr int NWARPS   = BLOCK / 32;             // 14
constexpr int SMEM_BYTES = SM_WARP + NWARPS * WARP_BLK;   // 231168

// gram pair index -> (a,b)
__device__ const unsigned char PA[36] = {0,0,0,0,0,0,0,0, 1,1,1,1,1,1,1, 2,2,2,2,2,2,
                                         3,3,3,3,3, 4,4,4,4, 5,5,5, 6,6, 7};
__device__ const unsigned char PB[36] = {0,1,2,3,4,5,6,7, 1,2,3,4,5,6,7, 2,3,4,5,6,7,
                                         3,4,5,6,7, 4,5,6,7, 5,6,7, 6,7, 7};

// ---------------- helpers ----------------
__device__ __forceinline__ void cvt2(float v0, float v1, uint32_t& hp, uint32_t& lp) {
    __nv_bfloat16 h0 = __float2bfloat16(v0), h1 = __float2bfloat16(v1);
    float r0 = v0 - __bfloat162float(h0), r1 = v1 - __bfloat162float(h1);
    __nv_bfloat16 l0 = __float2bfloat16(r0), l1 = __float2bfloat16(r1);
    __nv_bfloat162 hh; hh.x = h0; hh.y = h1;
    __nv_bfloat162 ll; ll.x = l0; ll.y = l1;
    hp = *reinterpret_cast<uint32_t*>(&hh);
    lp = *reinterpret_cast<uint32_t*>(&ll);
}

__device__ __forceinline__ void mma16816(float* d, const uint32_t* a, uint32_t b0, uint32_t b1) {
    asm volatile(
        "mma.sync.aligned.m16n8k16.row.col.f32.bf16.bf16.f32 "
        "{%0,%1,%2,%3}, {%4,%5,%6,%7}, {%8,%9}, {%0,%1,%2,%3};"
        : "+f"(d[0]), "+f"(d[1]), "+f"(d[2]), "+f"(d[3])
        : "r"(a[0]), "r"(a[1]), "r"(a[2]), "r"(a[3]), "r"(b0), "r"(b1));
}

// Convert a relu'd D (NT=8, 64 cols) into next layer's A-fragments and park in fragbuf.
// Thread slot: 68 words at fb + lane*68. aH u4 slots 0..7 ([mt*4+kt]), aL slots 8..15.
__device__ __forceinline__ void store_frags(uint32_t* fb, int lane, const float (&d)[2][8][4]) {
    uint4* base = reinterpret_cast<uint4*>(fb + lane * FWRD);
#pragma unroll
    for (int mt = 0; mt < 2; mt++)
#pragma unroll
        for (int kt = 0; kt < 4; kt++) {
            uint32_t h[4], l[4];
            cvt2(d[mt][2*kt][0],   d[mt][2*kt][1],   h[0], l[0]);
            cvt2(d[mt][2*kt][2],   d[mt][2*kt][3],   h[1], l[1]);
            cvt2(d[mt][2*kt+1][0], d[mt][2*kt+1][1], h[2], l[2]);
            cvt2(d[mt][2*kt+1][2], d[mt][2*kt+1][3], h[3], l[3]);
            base[mt * 4 + kt]     = make_uint4(h[0], h[1], h[2], h[3]);
            base[8 + mt * 4 + kt] = make_uint4(l[0], l[1], l[2], l[3]);
        }
}

// Layer with A-fragments streamed from fragbuf (K=64 fixed: KT=4).
template<int NT>
__device__ __forceinline__ void layer_fb(const uint32_t* fb, int lane, float (&dn)[2][NT][4],
                                         const uint16_t* WH, const uint16_t* WL,
                                         const float* bias, int gid, int tig, int ntOff = 0) {
    const uint4* base = reinterpret_cast<const uint4*>(fb + lane * FWRD);
#pragma unroll
    for (int mt = 0; mt < 2; mt++)
#pragma unroll
        for (int nt = 0; nt < NT; nt++) {
            float2 b = *reinterpret_cast<const float2*>(bias + (ntOff + nt) * 8 + 2 * tig);
            dn[mt][nt][0] = b.x; dn[mt][nt][1] = b.y;
            dn[mt][nt][2] = b.x; dn[mt][nt][3] = b.y;
        }
#pragma unroll
    for (int kt = 0; kt < 4; kt++) {
        uint4 h0v = base[kt], h1v = base[4 + kt];
        uint4 l0v = base[8 + kt], l1v = base[12 + kt];
        uint32_t aH[2][4] = {{h0v.x, h0v.y, h0v.z, h0v.w}, {h1v.x, h1v.y, h1v.z, h1v.w}};
        uint32_t aL[2][4] = {{l0v.x, l0v.y, l0v.z, l0v.w}, {l1v.x, l1v.y, l1v.z, l1v.w}};
#pragma unroll
        for (int nt = 0; nt < NT; nt++) {
            const uint32_t* ph = reinterpret_cast<const uint32_t*>(WH + ((ntOff+nt)*8+gid)*KPAD + kt*16 + 2*tig);
            const uint32_t* pl = reinterpret_cast<const uint32_t*>(WL + ((ntOff+nt)*8+gid)*KPAD + kt*16 + 2*tig);
            uint32_t bh0 = ph[0], bh1 = ph[4], bl0 = pl[0], bl1 = pl[4];
#pragma unroll
            for (int mt = 0; mt < 2; mt++) {
                mma16816(dn[mt][nt], aH[mt], bh0, bh1);
                mma16816(dn[mt][nt], aH[mt], bl0, bl1);
                mma16816(dn[mt][nt], aL[mt], bh0, bh1);
            }
        }
    }
}

// Layer with A from smem acts (hi/lo planes, APAD stride). K=48: KT=3.
template<int KT, int NT>
__device__ __forceinline__ void layer_sm(const uint16_t* actH, const uint16_t* actL,
                                         float (&dn)[2][NT][4],
                                         const uint16_t* WH, const uint16_t* WL,
                                         const float* bias, int gid, int tig) {
#pragma unroll
    for (int mt = 0; mt < 2; mt++)
#pragma unroll
        for (int nt = 0; nt < NT; nt++) {
            float2 b = *reinterpret_cast<const float2*>(bias + nt * 8 + 2 * tig);
            dn[mt][nt][0] = b.x; dn[mt][nt][1] = b.y;
            dn[mt][nt][2] = b.x; dn[mt][nt][3] = b.y;
        }
#pragma unroll
    for (int kt = 0; kt < KT; kt++) {
        uint32_t aH[2][4], aL[2][4];
#pragma unroll
        for (int mt = 0; mt < 2; mt++) {
            const int r0 = mt * 16 + gid, c0 = kt * 16 + 2 * tig;
            aH[mt][0] = *reinterpret_cast<const uint32_t*>(actH + r0 * APAD + c0);
            aH[mt][1] = *reinterpret_cast<const uint32_t*>(actH + (r0 + 8) * APAD + c0);
            aH[mt][2] = *reinterpret_cast<const uint32_t*>(actH + r0 * APAD + c0 + 8);
            aH[mt][3] = *reinterpret_cast<const uint32_t*>(actH + (r0 + 8) * APAD + c0 + 8);
            aL[mt][0] = *reinterpret_cast<const uint32_t*>(actL + r0 * APAD + c0);
            aL[mt][1] = *reinterpret_cast<const uint32_t*>(actL + (r0 + 8) * APAD + c0);
            aL[mt][2] = *reinterpret_cast<const uint32_t*>(actL + r0 * APAD + c0 + 8);
            aL[mt][3] = *reinterpret_cast<const uint32_t*>(actL + (r0 + 8) * APAD + c0 + 8);
        }
#pragma unroll
        for (int nt = 0; nt < NT; nt++) {
            const uint32_t* ph = reinterpret_cast<const uint32_t*>(WH + (nt*8+gid)*KPAD + kt*16 + 2*tig);
            const uint32_t* pl = reinterpret_cast<const uint32_t*>(WL + (nt*8+gid)*KPAD + kt*16 + 2*tig);
            uint32_t bh0 = ph[0], bh1 = ph[4], bl0 = pl[0], bl1 = pl[4];
#pragma unroll
            for (int mt = 0; mt < 2; mt++) {
                mma16816(dn[mt][nt], aH[mt], bh0, bh1);
                mma16816(dn[mt][nt], aH[mt], bl0, bl1);
                mma16816(dn[mt][nt], aL[mt], bh0, bh1);
            }
        }
    }
}

template<int NT>
__device__ __forceinline__ void relu_d(float (&d)[2][NT][4]) {
#pragma unroll
    for (int mt = 0; mt < 2; mt++)
#pragma unroll
        for (int nt = 0; nt < NT; nt++)
#pragma unroll
            for (int i = 0; i < 4; i++) d[mt][nt][i] = fmaxf(d[mt][nt][i], 0.f);
}

template<int NT>
__device__ __forceinline__ void store_D(float* dscr, const float (&d)[2][NT][4],
                                        int gid, int tig, int ntOff = 0) {
#pragma unroll
    for (int mt = 0; mt < 2; mt++)
#pragma unroll
        for (int nt = 0; nt < NT; nt++) {
            const int c = (ntOff + nt) * 8 + 2 * tig;
            dscr[(mt*16+gid)*DPAD + c]     = d[mt][nt][0];
            dscr[(mt*16+gid)*DPAD + c + 1] = d[mt][nt][1];
            dscr[(mt*16+gid+8)*DPAD + c]     = d[mt][nt][2];
            dscr[(mt*16+gid+8)*DPAD + c + 1] = d[mt][nt][3];
        }
}

__device__ __forceinline__ void write_acts(uint16_t* actH, uint16_t* actL, int lane, const float* xv) {
    uint32_t* ah = reinterpret_cast<uint32_t*>(actH + lane * APAD);
    uint32_t* al = reinterpret_cast<uint32_t*>(actL + lane * APAD);
#pragma unroll
    for (int c = 0; c < 48; c += 2) {
        float v0 = (c < 44) ? xv[c] : 0.f;
        float v1 = (c + 1 < 44) ? xv[c + 1] : 0.f;
        uint32_t hp, lp; cvt2(v0, v1, hp, lp);
        ah[c / 2] = hp; al[c / 2] = lp;
    }
}

__global__ void __launch_bounds__(BLOCK, 1) frame_gnn_mma_kernel(
    const float* __restrict__ state,
    const float* __restrict__ up_Z1_w, const float* __restrict__ up_h1_w, const float* __restrict__ up_h1_b,
    const float* __restrict__ up_g1_w1, const float* __restrict__ up_g1_b1,
    const float* __restrict__ up_g1_w2, const float* __restrict__ up_g1_b2,
    const float* __restrict__ up_Z2_w,
    const float* __restrict__ up_m_w1, const float* __restrict__ up_m_b1,
    const float* __restrict__ up_m_w2, const float* __restrict__ up_m_b2,
    const float* __restrict__ up_m_w3, const float* __restrict__ up_m_b3,
    const float* __restrict__ dn_g1_w1, const float* __restrict__ dn_g1_b1,
    const float* __restrict__ dn_g1_w2, const float* __restrict__ dn_g1_b2,
    const float* __restrict__ dn_Z2_w,
    const float* __restrict__ fr_w1, const float* __restrict__ fr_b1,
    const float* __restrict__ fr_w2, const float* __restrict__ fr_b2,
    const float* __restrict__ fr_w3, const float* __restrict__ fr_b3,
    float* __restrict__ out)
{
    extern __shared__ char smc[];
    float* scal = reinterpret_cast<float*>(smc);
    uint16_t* WT = reinterpret_cast<uint16_t*>(smc + SM_WT);
    const int tid = threadIdx.x;

    // ---------------- stage scalar weights (once) ----------------
    for (int i = tid; i < 104; i += BLOCK) scal[F_UH1W + i] = up_h1_w[i];
    for (int i = tid; i < 32; i += BLOCK)  scal[F_UZ1 + i] = up_Z1_w[i];
    for (int i = tid; i < 64; i += BLOCK) {
        const int k = i >> 3, j = i & 7;
        scal[F_G1W + i]  = up_g1_w1[k * 24 + j];
        scal[F_DG1W + i] = dn_g1_w1[k * 16 + j];
        scal[F_UZ2S + i] = up_Z2_w[k * 25 + j];
        scal[F_DZ2S + i] = dn_Z2_w[k * 17 + j];
        scal[F_B1 + i] = up_m_b1[i];  scal[F_B2 + i] = up_m_b2[i];
        scal[F_FB1 + i] = fr_b1[i];   scal[F_FB2 + i] = fr_b2[i];
    }
    for (int i = tid; i < 72; i += BLOCK) scal[F_B3 + i] = up_m_b3[i];
    if (tid < 8) {
        scal[F_UH1B + tid] = up_h1_b[tid];
        scal[F_G1B + tid]  = up_g1_b1[tid];
        scal[F_G2W + tid]  = up_g1_w2[tid];
        scal[F_UZ2Z + tid] = up_Z2_w[tid * 25 + 24];
        scal[F_DG1B + tid] = dn_g1_b1[tid];
        scal[F_DG2W + tid] = dn_g1_w2[tid];
        scal[F_DZ2Z + tid] = dn_Z2_w[tid * 17 + 16];
        scal[F_FB3 + tid]  = fr_b3[tid];
    }
    if (tid == 0) { scal[F_G2B] = up_g1_b2[0]; scal[F_DG2B] = dn_g1_b2[0]; }

    // ---------------- stage weight matrices (bf16 split, [n][KPAD], once) --------
    auto wsplit = [&](int offH, int offL, int idx, float v) {
        __nv_bfloat16 h = __float2bfloat16(v);
        __nv_bfloat16 l = __float2bfloat16(v - __bfloat162float(h));
        WT[offH + idx] = *reinterpret_cast<uint16_t*>(&h);
        WT[offL + idx] = *reinterpret_cast<uint16_t*>(&l);
    };
    for (int e = tid; e < 64 * KPAD; e += BLOCK) {   // L1 / F1 (folded gram)
        const int n = e / KPAD, k = e % KPAD;
        float v1 = 0.f, vf = 0.f;
        if (k < 36) {
            const int a = PA[k], b = PB[k];
            v1 = up_m_w1[n * 88 + a * 8 + b];
            vf = fr_w1[n * 80 + a * 8 + b];
            if (a != b) { v1 += up_m_w1[n * 88 + b * 8 + a]; vf += fr_w1[n * 80 + b * 8 + a]; }
        } else if (k < 44) {
            v1 = up_m_w1[n * 88 + 64 + (k - 36)];
            vf = fr_w1[n * 80 + 64 + (k - 36)];
        }
        wsplit(WH_L1, WL_L1, e, v1);
        wsplit(WH_F1, WL_F1, e, vf);
    }
    for (int e = tid; e < 64 * KPAD; e += BLOCK) {   // L2 / F2
        const int n = e / KPAD, k = e % KPAD;
        float v2 = (k < 64) ? up_m_w2[n * 64 + k] : 0.f;
        float vg = (k < 64) ? fr_w2[n * 64 + k] : 0.f;
        wsplit(WH_L2, WL_L2, e, v2);
        wsplit(WH_F2, WL_F2, e, vg);
    }
    for (int e = tid; e < 72 * KPAD; e += BLOCK) {   // L3
        const int n = e / KPAD, k = e % KPAD;
        wsplit(WH_L3, WL_L3, e, (k < 64) ? up_m_w3[n * 64 + k] : 0.f);
    }
    for (int e = tid; e < 8 * KPAD; e += BLOCK) {    // F3
        const int n = e / KPAD, k = e % KPAD;
        wsplit(WH_F3, WL_F3, e, (k < 64) ? fr_w3[n * 64 + k] : 0.f);
    }
    __syncthreads();

    const int w = tid >> 5, lane = tid & 31;
    const int gid = lane >> 2, tig = lane & 3;
    uint16_t* actH = reinterpret_cast<uint16_t*>(smc + SM_WARP + w * WARP_BLK);
    uint16_t* actL = actH + 32 * APAD;
    float* dscr = reinterpret_cast<float*>(smc + SM_WARP + w * WARP_BLK);
    uint32_t* fb = reinterpret_cast<uint32_t*>(smc + SM_WARP + w * WARP_BLK);

    // ---------------- persistent chunk loop ----------------
    for (int blk = blockIdx.x; blk < NBLKS; blk += GRID) {
        int row = blk * BLOCK + tid;
        if (row >= NROWS) row = NROWS - 1;   // dup rows write identical values
        const float* s = state + (size_t)row * 25;
        float* o = out + (size_t)row * 25;

        // ---------------- front (SIMT) ----------------
        float h0[13];
#pragma unroll
        for (int i = 0; i < 4; i++) { float v = s[i]; h0[i] = v; o[i] = v; }
#pragma unroll
        for (int i = 0; i < 9; i++) { float v = s[16 + i]; h0[4 + i] = v; o[16 + i] = v; }
        float hm8[8];
#pragma unroll
        for (int k = 0; k < 8; k++) {
            float a = scal[F_UH1B + k];
#pragma unroll
            for (int i = 0; i < 13; i++) a += h0[i] * scal[F_UH1W + k * 13 + i];
            hm8[k] = fmaxf(a, 0.f);
        }
        float gs = scal[F_G2B];
#pragma unroll
        for (int k = 0; k < 8; k++) {
            float a = scal[F_G1B + k];
#pragma unroll
            for (int i = 0; i < 8; i++) a += hm8[i] * scal[F_G1W + k * 8 + i];
            gs += fmaxf(a, 0.f) * scal[F_G2W + k];
        }
        float Zm0[8], Zm1[8], Zm2[8];
        {
            float Z0x[4], Z0y[4], Z0z[4];
#pragma unroll
            for (int j = 0; j < 4; j++) { Z0x[j] = s[4 + 3 * j]; Z0y[j] = s[5 + 3 * j]; Z0z[j] = s[6 + 3 * j]; }
            float Zu0[8], Zu1[8], Zu2[8];
#pragma unroll
            for (int k = 0; k < 8; k++) {
                float a0 = 0.f, a1 = 0.f, a2 = 0.f;
#pragma unroll
                for (int j = 0; j < 4; j++) {
                    float wv = scal[F_UZ1 + k * 4 + j];
                    a0 += Z0x[j] * wv; a1 += Z0y[j] * wv; a2 += Z0z[j] * wv;
                }
                Zu0[k] = a0; Zu1[k] = a1; Zu2[k] = a2;
            }
#pragma unroll
            for (int k = 0; k < 8; k++) {
                float a0 = 0.f, a1 = 0.f, a2 = 0.f;
#pragma unroll
                for (int m = 0; m < 8; m++) {
                    float wv = scal[F_UZ2S + k * 8 + m];
                    a0 += Zu0[m] * wv; a1 += Zu1[m] * wv; a2 += Zu2[m] * wv;
                }
                a2 += gs * scal[F_UZ2Z + k];
                Zm0[k] = a0; Zm1[k] = a1; Zm2[k] = a2;
            }
        }
        float xv[44], nrm = 0.f;
        {
            int p = 0;
#pragma unroll
            for (int a = 0; a < 8; a++)
#pragma unroll
                for (int b = a; b < 8; b++) {
                    float v = Zm0[a] * Zm0[b] + Zm1[a] * Zm1[b] + Zm2[a] * Zm2[b];
                    xv[p] = v;
                    nrm += (a == b) ? v * v : 2.f * v * v;
                    p++;
                }
        }
#pragma unroll
        for (int j = 0; j < 8; j++) xv[36 + j] = hm8[j];
        const float invFn = 1.f / (sqrtf(nrm) + 1.f);

        write_acts(actH, actL, lane, xv);
        __syncwarp();

        // ---------------- up_m chain: L1 -> (fb) -> L2 -> (fb) -> L3 -------------
        {
            float d1[2][8][4];
            layer_sm<3, 8>(actH, actL, d1, WT + WH_L1, WT + WL_L1, scal + F_B1, gid, tig);
            relu_d<8>(d1);
            __syncwarp();          // acts reads done before fragbuf overwrites region
            store_frags(fb, lane, d1);
        }
        {
            float d2[2][8][4];
            layer_fb<8>(fb, lane, d2, WT + WH_L2, WT + WL_L2, scal + F_B2, gid, tig);
            relu_d<8>(d2);
            store_frags(fb, lane, d2);   // per-thread slot: no cross-lane hazard
        }
        {
            float d3[2][9][4];
            layer_fb<9>(fb, lane, d3, WT + WH_L3, WT + WL_L3, scal + F_B3, gid, tig);
            __syncwarp();          // all fragbuf reads done before D overwrites region
            store_D<9>(dscr, d3, gid, tig);
        }
        __syncwarp();

        // ---------------- L3 post (row-coupled SIMT, streamed from smem) ---------
        float Yx[8], Yy[8], invFn2;
        {
            const float* dr = dscr + lane * DPAD;
            float uZ0[8], uZ1[8], uZ2[8], hm2[8];
#pragma unroll
            for (int k = 0; k < 8; k++) { uZ0[k] = 0.f; uZ1[k] = 0.f; uZ2[k] = 0.f; }
#pragma unroll
            for (int j = 0; j < 8; j++) {
                const float zj0 = Zm0[j], zj1 = Zm1[j], zj2 = Zm2[j];
#pragma unroll
                for (int k = 0; k < 8; k++) {
                    float m = dr[j * 8 + k] * invFn;   // bias baked into acc init
                    uZ0[k] += zj0 * m; uZ1[k] += zj1 * m; uZ2[k] += zj2 * m;
                }
            }
#pragma unroll
            for (int j = 0; j < 8; j++)
                hm2[j] = fmaxf(dr[64 + j] * invFn, 0.f);
            float gs2 = scal[F_DG2B];
#pragma unroll
            for (int k = 0; k < 8; k++) {
                float a = scal[F_DG1B + k];
#pragma unroll
                for (int i = 0; i < 8; i++) a += hm2[i] * scal[F_DG1W + k * 8 + i];
                gs2 += fmaxf(a, 0.f) * scal[F_DG2W + k];
            }
            float Yz[8];
#pragma unroll
            for (int k = 0; k < 8; k++) {
                float a0 = 0.f, a1 = 0.f, a2 = 0.f;
#pragma unroll
                for (int j = 0; j < 8; j++) {
                    float wv = scal[F_DZ2S + k * 8 + j];
                    a0 += uZ0[j] * wv; a1 += uZ1[j] * wv; a2 += uZ2[j] * wv;
                }
                a2 += gs2 * scal[F_DZ2Z + k];
                Yx[k] = a0; Yy[k] = a1; Yz[k] = a2;
            }
            float nrm2 = 0.f;
            int p = 0;
#pragma unroll
            for (int a = 0; a < 8; a++)
#pragma unroll
                for (int b = a; b < 8; b++) {
                    float v = Yx[a] * Yx[b] + Yy[a] * Yy[b] + Yz[a] * Yz[b];
                    xv[p] = v;
                    nrm2 += (a == b) ? v * v : 2.f * v * v;
                    p++;
                }
#pragma unroll
            for (int j = 0; j < 8; j++) xv[36 + j] = hm2[j];
            invFn2 = 1.f / (sqrtf(nrm2) + 1.f);
        }
        __syncwarp();              // D reads done before acts overwrite
        write_acts(actH, actL, lane, xv);
        __syncwarp();

        // ---------------- fr chain: F1 -> (fb) -> F2 -> (fb) -> F3 ---------------
        {
            float f1[2][8][4];
            layer_sm<3, 8>(actH, actL, f1, WT + WH_F1, WT + WL_F1, scal + F_FB1, gid, tig);
            relu_d<8>(f1);
            __syncwarp();          // acts reads done before fragbuf overwrites
            store_frags(fb, lane, f1);
        }
        {
            float f2[2][8][4];
            layer_fb<8>(fb, lane, f2, WT + WH_F2, WT + WL_F2, scal + F_FB2, gid, tig);
            relu_d<8>(f2);
            store_frags(fb, lane, f2);
        }
        {
            float f3[2][1][4];
            layer_fb<1>(fb, lane, f3, WT + WH_F3, WT + WL_F3, scal + F_FB3, gid, tig);
            __syncwarp();          // fragbuf reads done before D overwrites
            store_D<1>(dscr, f3, gid, tig);
        }
        __syncwarp();

        // ---------------- frame + rotation + writeback (frv streamed) ------------
        float fx = 0.f, fy = 0.f;
        {
            const float* dr = dscr + lane * DPAD;
#pragma unroll
            for (int k = 0; k < 8; k++) {
                float fv = dr[k] * invFn2;
                fx += Yx[k] * fv; fy += Yy[k] * fv;
            }
        }
        const float nn = sqrtf(fx * fx + fy * fy) + 1e-6f;
        const float u1x = fx / nn, u1y = fy / nn;
#pragma unroll
        for (int j = 0; j < 4; j++) {
            const float zx = __ldg(&s[4 + 3 * j]);
            const float zy = __ldg(&s[5 + 3 * j]);
            const float zz = __ldg(&s[6 + 3 * j]);
            o[4 + 3 * j]     = u1x * zx + u1y * zy;
            o[4 + 3 * j + 1] = -u1y * zx + u1x * zy;
            o[4 + 3 * j + 2] = zz;
        }
        __syncwarp();              // dscr reads done before next chunk's acts
    }
}

extern "C" void kernel_launch(void* const* d_in, const int* in_sizes, int n_in,
                              void* d_out, int out_size) {
    (void)in_sizes; (void)n_in; (void)out_size;
    cudaFuncSetAttribute(frame_gnn_mma_kernel, cudaFuncAttributeMaxDynamicSharedMemorySize,
                         SMEM_BYTES);
    frame_gnn_mma_kernel<<<GRID, BLOCK, SMEM_BYTES>>>(
        (const float*)d_in[0],
        (const float*)d_in[1], (const float*)d_in[2], (const float*)d_in[3],
        (const float*)d_in[4], (const float*)d_in[5], (const float*)d_in[6], (const float*)d_in[7],
        (const float*)d_in[8],
        (const float*)d_in[9], (const float*)d_in[10], (const float*)d_in[11], (const float*)d_in[12],
        (const float*)d_in[13], (const float*)d_in[14],
        (const float*)d_in[15], (const float*)d_in[16], (const float*)d_in[17], (const float*)d_in[18],
        (const float*)d_in[19],
        (const float*)d_in[20], (const float*)d_in[21], (const float*)d_in[22], (const float*)d_in[23],
        (const float*)d_in[24], (const float*)d_in[25],
        (float*)d_out);
}